// round 6
// baseline (speedup 1.0000x reference)
#include <cuda_runtime.h>
#include <cuda_bf16.h>
#include <mma.h>
#include <math.h>
#include <stdint.h>

using namespace nvcuda;
typedef __nv_bfloat16 bf16;

// ---------------- problem constants ----------------
#define Bc     16
#define HDIM   224
#define CC     96
#define LL     (HDIM*HDIM)
#define NTOK   (Bc*LL)              // 802816
#define WSZ    7
#define NN     49
#define NWIN   32
#define BW     (Bc*NWIN*NWIN)       // 16384
#define NHH    3
#define HD     32
#define MLPH   384
#define SHIFTV 3
#define SCALEV 0.17677669529663687f
#define NUMTILES (NTOK/128)         // 6272
#define GRID   148

static const long long YE = (long long)NTOK * CC;
static const long long AE = (long long)BW * NHH * NN * NN;

// ---------------- scratch ----------------
__device__ bf16 g_hw [(size_t)NTOK * CC];
__device__ bf16 g_qkv[(size_t)NTOK * 288];
__device__ bf16 g_att[(size_t)NTOK * CC];
__device__ bf16 g_hid[(size_t)NTOK * MLPH];

// ---------------- helpers ----------------
__device__ __forceinline__ uint32_t smem_u32(const void* p) {
    uint32_t a;
    asm("{ .reg .u64 t; cvta.to.shared.u64 t, %1; cvt.u32.u64 %0, t; }" : "=r"(a) : "l"(p));
    return a;
}
__device__ __forceinline__ void cp16(void* d, const void* s) {
    asm volatile("cp.async.cg.shared.global [%0], [%1], 16;" :: "r"(smem_u32(d)), "l"(s));
}
#define CPC() asm volatile("cp.async.commit_group;" ::: "memory")
#define CPW() asm volatile("cp.async.wait_group 0;" ::: "memory")

__device__ __forceinline__ void ldm_x4(uint32_t& r0, uint32_t& r1, uint32_t& r2, uint32_t& r3, uint32_t addr) {
    asm volatile("ldmatrix.sync.aligned.m8n8.x4.shared.b16 {%0,%1,%2,%3}, [%4];"
                 : "=r"(r0), "=r"(r1), "=r"(r2), "=r"(r3) : "r"(addr));
}
__device__ __forceinline__ void ldm_x4t(uint32_t& r0, uint32_t& r1, uint32_t& r2, uint32_t& r3, uint32_t addr) {
    asm volatile("ldmatrix.sync.aligned.m8n8.x4.trans.shared.b16 {%0,%1,%2,%3}, [%4];"
                 : "=r"(r0), "=r"(r1), "=r"(r2), "=r"(r3) : "r"(addr));
}
__device__ __forceinline__ void mma16816(float* c, uint32_t a0, uint32_t a1, uint32_t a2, uint32_t a3,
                                         uint32_t b0, uint32_t b1) {
    asm volatile("mma.sync.aligned.m16n8k16.row.col.f32.bf16.bf16.f32 "
                 "{%0,%1,%2,%3}, {%4,%5,%6,%7}, {%8,%9}, {%0,%1,%2,%3};"
                 : "+f"(c[0]), "+f"(c[1]), "+f"(c[2]), "+f"(c[3])
                 : "r"(a0), "r"(a1), "r"(a2), "r"(a3), "r"(b0), "r"(b1));
}

__device__ __forceinline__ float wred(float v) {
    #pragma unroll
    for (int o = 16; o; o >>= 1) v += __shfl_xor_sync(0xffffffffu, v, o);
    return v;
}

__device__ __forceinline__ int winrow_to_token(int row) {
    int n  = row % NN;  int w = row / NN;
    int wj = w % NWIN;  int t = w / NWIN;
    int wi = t % NWIN;  int bb = t / NWIN;
    int i = n / WSZ, j = n % WSZ;
    int r = wi*WSZ + i + SHIFTV; if (r >= HDIM) r -= HDIM;
    int c = wj*WSZ + j + SHIFTV; if (c >= HDIM) c -= HDIM;
    return bb*LL + r*HDIM + c;
}

// =====================================================================
// qkv kernel: fused LN1 + shifted-window gather + GEMM (96 -> 288)
// direct x loads, no staging -> 86KB smem -> 2 CTAs/SM
// =====================================================================
__global__ void __launch_bounds__(512, 2)
qkv_kernel(const float* __restrict__ x, const float* __restrict__ Wq,
           const float* __restrict__ bq, const float* __restrict__ g1,
           const float* __restrict__ b1, bf16* __restrict__ out)
{
    extern __shared__ __align__(16) char sm[];
    bf16*  sW   = (bf16*)sm;                       // 96*296*2  = 56832
    bf16*  sA   = (bf16*)(sm + 56832);             // 128*104*2 = 26624
    int*   stok = (int*)(sm + 83456);              // 512
    float* sbias= (float*)(sm + 83968);            // 1152
    float* sg   = (float*)(sm + 85120);            // 384
    float* sb   = (float*)(sm + 85504);            // 384  (total 85888)

    const int tid = threadIdx.x, warp = tid >> 5, lane = tid & 31;
    const int mw = warp >> 1, nw = warp & 1;

    for (int i = tid; i < 96*288; i += 512) { int k = i/288, n = i%288; sW[k*296+n] = __float2bfloat16(Wq[i]); }
    for (int i = tid; i < 288; i += 512) sbias[i] = bq[i];
    if (tid < 96) { sg[tid] = g1[tid]; sb[tid] = b1[tid]; }

    const uint32_t aBase = smem_u32(sA) + ((mw*16 + (lane & 15))*104 + (lane >> 4)*8) * 2;
    const uint32_t wBase = smem_u32(sW) + (((lane & 7) + ((lane >> 3) & 1)*8)*296 + (lane >> 4)*8) * 2;
    const float gg0 = g1[lane], gg1 = g1[lane+32], gg2 = g1[lane+64];
    const float bb0 = b1[lane], bb1 = b1[lane+32], bb2 = b1[lane+64];

    for (int tile = blockIdx.x; tile < NUMTILES; tile += 2*GRID) {
        if (tid < 128) stok[tid] = winrow_to_token(tile*128 + tid);
        __syncthreads();   // stok visible; previous iter's ldmatrix reads of sA done

        // LN1: 16 warps x 8 rows, loads batched for MLP
        int tk[8];
        #pragma unroll
        for (int rr = 0; rr < 8; rr++) tk[rr] = stok[warp*8 + rr];
        float v0[8], v1[8], v2[8];
        #pragma unroll
        for (int rr = 0; rr < 8; rr++) {
            const float* xp = x + (size_t)tk[rr]*96;
            v0[rr] = __ldg(xp+lane); v1[rr] = __ldg(xp+lane+32); v2[rr] = __ldg(xp+lane+64);
        }
        #pragma unroll
        for (int rr = 0; rr < 8; rr++) {
            int r = warp*8 + rr;
            float mu = wred(v0[rr]+v1[rr]+v2[rr]) * (1.f/96.f);
            float d0 = v0[rr]-mu, d1 = v1[rr]-mu, d2 = v2[rr]-mu;
            float var = wred(d0*d0 + d1*d1 + d2*d2) * (1.f/96.f);
            float rs = rsqrtf(var + 1e-5f);
            sA[r*104+lane]    = __float2bfloat16(d0*rs*gg0 + bb0);
            sA[r*104+lane+32] = __float2bfloat16(d1*rs*gg1 + bb1);
            sA[r*104+lane+64] = __float2bfloat16(d2*rs*gg2 + bb2);
        }
        __syncthreads();

        const int r0 = tile*128 + mw*16 + (lane >> 2);
        const int cl = (lane & 3)*2;
        #pragma unroll
        for (int c = 0; c < 3; c++) {
            float acc[6][4];
            #pragma unroll
            for (int f = 0; f < 6; f++) { acc[f][0]=0.f; acc[f][1]=0.f; acc[f][2]=0.f; acc[f][3]=0.f; }
            #pragma unroll
            for (int ks = 0; ks < 6; ks++) {
                uint32_t a0,a1,a2,a3;
                ldm_x4(a0,a1,a2,a3, aBase + ks*32);
                #pragma unroll
                for (int p = 0; p < 3; p++) {
                    uint32_t b0,b1,b2,b3;
                    ldm_x4t(b0,b1,b2,b3, wBase + (ks*16*296 + c*96 + nw*48 + p*16)*2);
                    mma16816(acc[2*p],   a0,a1,a2,a3, b0,b1);
                    mma16816(acc[2*p+1], a0,a1,a2,a3, b2,b3);
                }
            }
            #pragma unroll
            for (int f = 0; f < 6; f++) {
                int col = c*96 + nw*48 + f*8 + cl;
                float bz0 = sbias[col], bz1 = sbias[col+1];
                __nv_bfloat162 p0 = __floats2bfloat162_rn(acc[f][0]+bz0, acc[f][1]+bz1);
                __nv_bfloat162 p1 = __floats2bfloat162_rn(acc[f][2]+bz0, acc[f][3]+bz1);
                *(uint32_t*)(out + (size_t)r0*288 + col)     = *(uint32_t*)&p0;
                *(uint32_t*)(out + (size_t)(r0+8)*288 + col) = *(uint32_t*)&p1;
            }
        }
    }
}

// =====================================================================
// proj kernel (WMMA + staging, LN2 fused) -- unchanged
// =====================================================================
__global__ void __launch_bounds__(512, 1)
proj_kernel(const bf16* __restrict__ A, const float* __restrict__ Wp,
            const float* __restrict__ bp, const float* __restrict__ x,
            const float* __restrict__ g2, const float* __restrict__ b2,
            float* __restrict__ y, bf16* __restrict__ hw)
{
    extern __shared__ __align__(16) char sm[];
    bf16*  sW   = (bf16*)sm;                        // 19968
    bf16*  sA0  = (bf16*)(sm + 19968);
    bf16*  sA1  = (bf16*)(sm + 46592);
    float* stag = (float*)(sm + 73216);             // 51200
    float* rst0 = (float*)(sm + 124416);
    float* rst1 = (float*)(sm + 173568);
    int*   stok = (int*)(sm + 222720);
    float* sbias= (float*)(sm + 223744);
    float* sg   = (float*)(sm + 224128);
    float* sb   = (float*)(sm + 224512);            // total 224896

    const int tid = threadIdx.x, warp = tid >> 5, lane = tid & 31;
    const int mw = warp >> 1, nw = warp & 1;

    for (int i = tid; i < 96*96; i += 512) { int k = i/96, n = i%96; sW[k*104+n] = __float2bfloat16(Wp[i]); }
    if (tid < 96) { sbias[tid] = bp[tid]; sg[tid] = g2[tid]; sb[tid] = b2[tid]; }

    int tile = blockIdx.x, buf = 0;
    if (tid < 128) stok[tid] = winrow_to_token(tile*128 + tid);
    __syncthreads();
    {
        const bf16* Ag = A + (size_t)tile*128*96;
        for (int idx = tid; idx < 1536; idx += 512) { int r = idx/12, c = idx%12; cp16(sA0 + r*104 + c*8, Ag + r*96 + c*8); }
        for (int idx = tid; idx < 3072; idx += 512) { int r = idx/24, c = idx%24; cp16(rst0 + r*96 + c*4, x + (size_t)stok[r]*96 + c*4); }
    }
    CPC();

    for (; tile < NUMTILES; tile += GRID) {
        CPW(); __syncthreads();
        bf16*  sA  = buf ? sA1 : sA0;
        float* rst = buf ? rst1 : rst0;

        int nt = tile + GRID;
        int nb = buf ^ 1;
        if (tid < 128 && nt < NUMTILES) stok[nb*128 + tid] = winrow_to_token(nt*128 + tid);
        __syncthreads();
        if (nt < NUMTILES) {
            bf16*  sAn  = nb ? sA1 : sA0;
            float* rstn = nb ? rst1 : rst0;
            const int* st = stok + nb*128;
            const bf16* Ag = A + (size_t)nt*128*96;
            for (int idx = tid; idx < 1536; idx += 512) { int r = idx/12, c = idx%12; cp16(sAn + r*104 + c*8, Ag + r*96 + c*8); }
            for (int idx = tid; idx < 3072; idx += 512) { int r = idx/24, c = idx%24; cp16(rstn + r*96 + c*4, x + (size_t)st[r]*96 + c*4); }
        }
        CPC();

        wmma::fragment<wmma::accumulator, 16, 16, 16, float> acc[3];
        #pragma unroll
        for (int f = 0; f < 3; f++) wmma::fill_fragment(acc[f], 0.f);
        #pragma unroll
        for (int ks = 0; ks < 6; ks++) {
            wmma::fragment<wmma::matrix_a, 16, 16, 16, bf16, wmma::row_major> af;
            wmma::load_matrix_sync(af, sA + (mw*16)*104 + ks*16, 104);
            #pragma unroll
            for (int f = 0; f < 3; f++) {
                wmma::fragment<wmma::matrix_b, 16, 16, 16, bf16, wmma::row_major> bfr;
                wmma::load_matrix_sync(bfr, sW + (ks*16)*104 + nw*48 + f*16, 104);
                wmma::mma_sync(acc[f], af, bfr, acc[f]);
            }
        }
        __syncthreads();
        #pragma unroll
        for (int f = 0; f < 3; f++)
            wmma::store_matrix_sync(stag + (mw*16)*100 + nw*48 + f*16, acc[f], 100, wmma::mem_row_major);
        __syncthreads();

        const int* st = stok + buf*128;
        #pragma unroll
        for (int rr = 0; rr < 8; rr++) {
            int r = warp*8 + rr;
            int tk = st[r];
            float a0 = stag[r*100+lane]    + sbias[lane]    + rst[r*96+lane];
            float a1 = stag[r*100+lane+32] + sbias[lane+32] + rst[r*96+lane+32];
            float a2 = stag[r*100+lane+64] + sbias[lane+64] + rst[r*96+lane+64];
            float mu = wred(a0+a1+a2) * (1.f/96.f);
            float d0 = a0-mu, d1 = a1-mu, d2 = a2-mu;
            float var = wred(d0*d0 + d1*d1 + d2*d2) * (1.f/96.f);
            float rs = rsqrtf(var + 1e-5f);
            size_t o = (size_t)tk * 96;
            y[o+lane]    = a0;  y[o+lane+32] = a1;  y[o+lane+64] = a2;
            hw[o+lane]    = __float2bfloat16(d0*rs*sg[lane]    + sb[lane]);
            hw[o+lane+32] = __float2bfloat16(d1*rs*sg[lane+32] + sb[lane+32]);
            hw[o+lane+64] = __float2bfloat16(d2*rs*sg[lane+64] + sb[lane+64]);
        }
        __syncthreads();
        buf ^= 1;
    }
}

// =====================================================================
// fc1 kernel: GEMM (96 -> 384) + GELU, N split across CTA pairs
// smem 92KB -> 2 CTAs/SM
// =====================================================================
__global__ void __launch_bounds__(512, 2)
fc1_kernel(const bf16* __restrict__ A, const float* __restrict__ W1,
           const float* __restrict__ bb, bf16* __restrict__ out)
{
    extern __shared__ __align__(16) char sm[];
    bf16*  sW   = (bf16*)sm;                        // 96*200*2 = 38400
    bf16*  sA0  = (bf16*)(sm + 38400);              // 26624
    bf16*  sA1  = (bf16*)(sm + 65024);              // 26624
    float* sbias= (float*)(sm + 91648);             // 768 (total 92416)

    const int tid = threadIdx.x, warp = tid >> 5, lane = tid & 31;
    const int mw = warp >> 1, nw = warp & 1;
    const int half = blockIdx.x & 1;
    const int tstart = blockIdx.x >> 1;

    for (int i = tid; i < 96*192; i += 512) {
        int k = i/192, n = i%192;
        sW[k*200+n] = __float2bfloat16(W1[(size_t)k*384 + half*192 + n]);
    }
    for (int i = tid; i < 192; i += 512) sbias[i] = bb[half*192 + i];

    const uint32_t wBase = smem_u32(sW) + (((lane & 7) + ((lane >> 3) & 1)*8)*200 + (lane >> 4)*8) * 2;
    const uint32_t aOff  = ((mw*16 + (lane & 15))*104 + (lane >> 4)*8) * 2;

    int tile = tstart, buf = 0;
    {
        const bf16* Ag = A + (size_t)tile*128*96;
        for (int idx = tid; idx < 1536; idx += 512) { int r = idx/12, c = idx%12; cp16(sA0 + r*104 + c*8, Ag + r*96 + c*8); }
    }
    CPC();

    for (; tile < NUMTILES; tile += GRID) {
        CPW(); __syncthreads();
        uint32_t aBase = smem_u32(buf ? sA1 : sA0) + aOff;
        int nt = tile + GRID;
        if (nt < NUMTILES) {
            bf16* sAn = (buf^1) ? sA1 : sA0;
            const bf16* Ag = A + (size_t)nt*128*96;
            for (int idx = tid; idx < 1536; idx += 512) { int r = idx/12, c = idx%12; cp16(sAn + r*104 + c*8, Ag + r*96 + c*8); }
        }
        CPC();

        const int r0 = tile*128 + mw*16 + (lane >> 2);
        const int cl = (lane & 3)*2;
        #pragma unroll
        for (int c = 0; c < 2; c++) {
            float acc[6][4];
            #pragma unroll
            for (int f = 0; f < 6; f++) { acc[f][0]=0.f; acc[f][1]=0.f; acc[f][2]=0.f; acc[f][3]=0.f; }
            #pragma unroll
            for (int ks = 0; ks < 6; ks++) {
                uint32_t a0,a1,a2,a3;
                ldm_x4(a0,a1,a2,a3, aBase + ks*32);
                #pragma unroll
                for (int p = 0; p < 3; p++) {
                    uint32_t b0,b1,b2,b3;
                    ldm_x4t(b0,b1,b2,b3, wBase + (ks*16*200 + c*96 + nw*48 + p*16)*2);
                    mma16816(acc[2*p],   a0,a1,a2,a3, b0,b1);
                    mma16816(acc[2*p+1], a0,a1,a2,a3, b2,b3);
                }
            }
            #pragma unroll
            for (int f = 0; f < 6; f++) {
                int scol = c*96 + nw*48 + f*8 + cl;
                int col  = half*192 + scol;
                float u0 = acc[f][0] + sbias[scol];
                float u1 = acc[f][1] + sbias[scol+1];
                float u2 = acc[f][2] + sbias[scol];
                float u3 = acc[f][3] + sbias[scol+1];
                u0 = 0.5f*u0*(1.f + erff(u0*0.70710678118654752f));
                u1 = 0.5f*u1*(1.f + erff(u1*0.70710678118654752f));
                u2 = 0.5f*u2*(1.f + erff(u2*0.70710678118654752f));
                u3 = 0.5f*u3*(1.f + erff(u3*0.70710678118654752f));
                __nv_bfloat162 p0 = __floats2bfloat162_rn(u0, u1);
                __nv_bfloat162 p1 = __floats2bfloat162_rn(u2, u3);
                *(uint32_t*)(out + (size_t)r0*384 + col)     = *(uint32_t*)&p0;
                *(uint32_t*)(out + (size_t)(r0+8)*384 + col) = *(uint32_t*)&p1;
            }
        }
        buf ^= 1;
    }
}

// =====================================================================
// fc2 kernel: GEMM (384 -> 96) + residual += into y (unchanged)
// =====================================================================
__global__ void __launch_bounds__(512, 1)
fc2_kernel(const bf16* __restrict__ A, const float* __restrict__ W2,
           const float* __restrict__ bb, float* __restrict__ y)
{
    extern __shared__ __align__(16) char sm[];
    bf16*  sW   = (bf16*)sm;                        // 384*104*2 = 79872
    bf16*  sA0  = (bf16*)(sm + 79872);              // 26624
    bf16*  sA1  = (bf16*)(sm + 106496);             // 26624
    float* sbias= (float*)(sm + 133120);            // 384 (total 133504)

    const int tid = threadIdx.x, warp = tid >> 5, lane = tid & 31;
    const int mw = warp >> 1, nw = warp & 1;

    for (int i = tid; i < 384*96; i += 512) { int k = i/96, n = i%96; sW[k*104+n] = __float2bfloat16(W2[i]); }
    if (tid < 96) sbias[tid] = bb[tid];

    const uint32_t wBase = smem_u32(sW) + (((lane & 7) + ((lane >> 3) & 1)*8)*104 + (lane >> 4)*8) * 2;
    const uint32_t aOff  = ((mw*16 + (lane & 15))*104 + (lane >> 4)*8) * 2;
    const uint32_t sA0u = smem_u32(sA0), sA1u = smem_u32(sA1);

    int tile = blockIdx.x;
    {
        const bf16* Ag = A + (size_t)tile*128*384;
        for (int idx = tid; idx < 1536; idx += 512) { int r = idx/12, c = idx%12; cp16(sA0 + r*104 + c*8, Ag + r*384 + c*8); }
    }
    CPC();
    __syncthreads();

    for (; tile < NUMTILES; tile += GRID) {
        float acc[6][4];
        #pragma unroll
        for (int f = 0; f < 6; f++) { acc[f][0]=0.f; acc[f][1]=0.f; acc[f][2]=0.f; acc[f][3]=0.f; }

        #pragma unroll
        for (int kc = 0; kc < 4; kc++) {
            CPW(); __syncthreads();
            int ntile = (kc < 3) ? tile : tile + GRID;
            int nkc   = (kc < 3) ? kc + 1 : 0;
            if (ntile < NUMTILES) {
                bf16* sAn = ((kc+1) & 1) ? sA1 : sA0;
                const bf16* Ag = A + (size_t)ntile*128*384 + nkc*96;
                for (int idx = tid; idx < 1536; idx += 512) { int r = idx/12, c = idx%12; cp16(sAn + r*104 + c*8, Ag + r*384 + c*8); }
            }
            CPC();

            uint32_t aBase = ((kc & 1) ? sA1u : sA0u) + aOff;
            #pragma unroll
            for (int ks = 0; ks < 6; ks++) {
                uint32_t a0,a1,a2,a3;
                ldm_x4(a0,a1,a2,a3, aBase + ks*32);
                #pragma unroll
                for (int p = 0; p < 3; p++) {
                    uint32_t b0,b1,b2,b3;
                    ldm_x4t(b0,b1,b2,b3, wBase + ((kc*96 + ks*16)*104 + nw*48 + p*16)*2);
                    mma16816(acc[2*p],   a0,a1,a2,a3, b0,b1);
                    mma16816(acc[2*p+1], a0,a1,a2,a3, b2,b3);
                }
            }
        }

        const int r0 = tile*128 + mw*16 + (lane >> 2);
        const int cl = (lane & 3)*2;
        #pragma unroll
        for (int f = 0; f < 6; f++) {
            int col = nw*48 + f*8 + cl;
            float bz0 = sbias[col], bz1 = sbias[col+1];
            float2* p0 = (float2*)(y + (size_t)r0*96 + col);
            float2* p1 = (float2*)(y + (size_t)(r0+8)*96 + col);
            float2 v0 = *p0, v1 = *p1;
            v0.x += acc[f][0] + bz0;  v0.y += acc[f][1] + bz1;
            v1.x += acc[f][2] + bz0;  v1.y += acc[f][3] + bz1;
            *p0 = v0;  *p1 = v1;
        }
    }
}

// =====================================================================
// window attention: 128 threads, lane-pair row split (16 dims/thread)
// =====================================================================
__global__ void __launch_bounds__(128)
attn_kernel(const bf16* __restrict__ qkv, const float* __restrict__ rpb,
            float* __restrict__ attn_w, bf16* __restrict__ outp) {
    const int blk = blockIdx.x;
    const int h = blk % NHH, w = blk / NHH;
    __shared__ float sk[NN*HD], sv[NN*HD];
    __shared__ float srpb[169];
    __shared__ float s_a[NN*53];
    const int tid = threadIdx.x;

    const bf16* base = qkv + (size_t)w * NN * 288 + h*HD;
    for (int idx = tid; idx < NN*8; idx += 128) {
        int n = idx >> 3, p = idx & 7;
        int which = p >> 2, ch = p & 3;           // 0=k, 1=v
        uint4 vv = *(const uint4*)(base + (size_t)n*288 + 96 + which*96 + ch*8);
        const __nv_bfloat162* b2 = (const __nv_bfloat162*)&vv;
        float* dst = (which == 0 ? sk : sv) + n*HD + ch*8;
        #pragma unroll
        for (int t = 0; t < 4; t++) { float2 f = __bfloat1622float2(b2[t]); dst[2*t] = f.x; dst[2*t+1] = f.y; }
    }
    for (int idx = tid; idx < 169; idx += 128) srpb[idx] = rpb[idx*NHH + h];
    __syncthreads();

    const int n = tid >> 1, half = tid & 1;
    const int nc = (n < NN) ? n : NN-1;
    const bool act = (n < NN);

    // q: 16 dims (this thread's half)
    float q[16];
    {
        const bf16* qp = base + (size_t)nc*288 + half*16;
        #pragma unroll
        for (int t = 0; t < 2; t++) {
            uint4 vv = ((const uint4*)qp)[t];
            const __nv_bfloat162* b2 = (const __nv_bfloat162*)&vv;
            #pragma unroll
            for (int u = 0; u < 4; u++) {
                float2 f = __bfloat1622float2(b2[u]);
                q[t*8 + 2*u]     = f.x * SCALEV;
                q[t*8 + 2*u + 1] = f.y * SCALEV;
            }
        }
    }
    const int bias0 = (nc/WSZ + 6)*13 + (nc%WSZ + 6);

    // QK^T: halves combined via shfl (all 128 threads execute the shfl)
    float mx = -1e30f;
    {
        int i2 = 0, j2 = 0;
        for (int m = 0; m < NN; m++) {
            const float4* kk4 = (const float4*)(sk + m*HD + half*16);
            float s0 = 0.f, s1 = 0.f, s2 = 0.f, s3 = 0.f;
            #pragma unroll
            for (int i = 0; i < 4; i++) {
                float4 kk = kk4[i];
                s0 += q[4*i]*kk.x; s1 += q[4*i+1]*kk.y; s2 += q[4*i+2]*kk.z; s3 += q[4*i+3]*kk.w;
            }
            float d = (s0 + s1) + (s2 + s3);
            d += __shfl_xor_sync(0xffffffffu, d, 1);
            d += srpb[bias0 - i2*13 - j2];
            if (act && half == 0) s_a[n*53 + m] = d;
            mx = fmaxf(mx, d);
            if (++j2 == WSZ) { j2 = 0; i2++; }
        }
    }
    if (act && half == 0) {
        float ss = 0.f;
        for (int m = 0; m < NN; m++) { float e = __expf(s_a[n*53 + m] - mx); s_a[n*53 + m] = e; ss += e; }
        float inv = 1.f / ss;
        for (int m = 0; m < NN; m++) s_a[n*53 + m] *= inv;
    }
    __syncthreads();

    if (attn_w) {
        float* ap = attn_w + (size_t)(w*NHH + h) * (NN*NN);
        for (int idx = tid; idx < NN*NN; idx += 128) ap[idx] = s_a[(idx/NN)*53 + idx % NN];
    }

    // AV: each thread handles 16 dims of its row
    {
        float4 o[4];
        #pragma unroll
        for (int i = 0; i < 4; i++) { o[i].x = 0.f; o[i].y = 0.f; o[i].z = 0.f; o[i].w = 0.f; }
        const float4* sv4 = (const float4*)sv;
        for (int m = 0; m < NN; m++) {
            float a = s_a[nc*53 + m];
            #pragma unroll
            for (int i = 0; i < 4; i++) {
                float4 vv = sv4[m*8 + half*4 + i];
                o[i].x += a*vv.x; o[i].y += a*vv.y; o[i].z += a*vv.z; o[i].w += a*vv.w;
            }
        }
        if (act) {
            bf16* op = outp + (size_t)(w*NN + n) * CC + h*HD + half*16;
            uint32_t pk[8];
            #pragma unroll
            for (int i = 0; i < 4; i++) {
                __nv_bfloat162 p0 = __floats2bfloat162_rn(o[i].x, o[i].y);
                __nv_bfloat162 p1 = __floats2bfloat162_rn(o[i].z, o[i].w);
                pk[2*i]   = *(uint32_t*)&p0;
                pk[2*i+1] = *(uint32_t*)&p1;
            }
            ((uint4*)op)[0] = ((const uint4*)pk)[0];
            ((uint4*)op)[1] = ((const uint4*)pk)[1];
        }
    }
}

// ---------------- launch ----------------
extern "C" void kernel_launch(void* const* d_in, const int* in_sizes, int n_in,
                              void* d_out, int out_size) {
    const float* x      = (const float*)d_in[0];
    const float* w_qkv  = (const float*)d_in[1];
    const float* b_qkv  = (const float*)d_in[2];
    const float* w_proj = (const float*)d_in[3];
    const float* b_proj = (const float*)d_in[4];
    const float* rpb    = (const float*)d_in[5];
    const float* gamma1 = (const float*)d_in[6];
    const float* beta1  = (const float*)d_in[7];
    const float* gamma2 = (const float*)d_in[8];
    const float* beta2  = (const float*)d_in[9];
    const float* w_fc1  = (const float*)d_in[10];
    const float* b_fc1  = (const float*)d_in[11];
    const float* w_fc2  = (const float*)d_in[12];
    const float* b_fc2  = (const float*)d_in[13];

    float* y = (float*)d_out;
    float* attn_w = ((long long)out_size >= YE + AE) ? (y + YE) : (float*)0;

    bf16 *p_hw, *p_qkv, *p_att, *p_hid;
    cudaGetSymbolAddress((void**)&p_hw,  g_hw);
    cudaGetSymbolAddress((void**)&p_qkv, g_qkv);
    cudaGetSymbolAddress((void**)&p_att, g_att);
    cudaGetSymbolAddress((void**)&p_hid, g_hid);

    const int SMQ = 85888, SMP = 224896, SM1 = 92416, SM2 = 133504;
    cudaFuncSetAttribute(qkv_kernel, cudaFuncAttributeMaxDynamicSharedMemorySize, SMQ);
    cudaFuncSetAttribute(proj_kernel, cudaFuncAttributeMaxDynamicSharedMemorySize, SMP);
    cudaFuncSetAttribute(fc1_kernel, cudaFuncAttributeMaxDynamicSharedMemorySize, SM1);
    cudaFuncSetAttribute(fc2_kernel, cudaFuncAttributeMaxDynamicSharedMemorySize, SM2);

    // 1) fused LN1 + gather + qkv GEMM (2 CTAs/SM)
    qkv_kernel<<<2*GRID, 512, SMQ>>>(x, w_qkv, b_qkv, gamma1, beta1, p_qkv);
    // 2) window attention (+ attn weights)
    attn_kernel<<<BW*NHH, 128>>>(p_qkv, rpb, attn_w, p_att);
    // 3) proj GEMM + scatter + residual + LN2 -> y, hw
    proj_kernel<<<GRID, 512, SMP>>>(p_att, w_proj, b_proj, x, gamma2, beta2, y, p_hw);
    // 4) fc1 + GELU (N-split, 2 CTAs/SM)
    fc1_kernel<<<2*GRID, 512, SM1>>>(p_hw, w_fc1, b_fc1, p_hid);
    // 5) fc2 + residual into y
    fc2_kernel<<<GRID, 512, SM2>>>(p_hid, w_fc2, b_fc2, y);
}

// round 7
// speedup vs baseline: 1.0351x; 1.0351x over previous
#include <cuda_runtime.h>
#include <cuda_bf16.h>
#include <mma.h>
#include <math.h>
#include <stdint.h>

using namespace nvcuda;
typedef __nv_bfloat16 bf16;

// ---------------- problem constants ----------------
#define Bc     16
#define HDIM   224
#define CC     96
#define LL     (HDIM*HDIM)
#define NTOK   (Bc*LL)              // 802816
#define WSZ    7
#define NN     49
#define NWIN   32
#define BW     (Bc*NWIN*NWIN)       // 16384
#define NHH    3
#define HD     32
#define MLPH   384
#define SHIFTV 3
#define SCALEV 0.17677669529663687f
#define NUMTILES (NTOK/128)         // 6272
#define GRID   148

static const long long YE = (long long)NTOK * CC;
static const long long AE = (long long)BW * NHH * NN * NN;

// ---------------- scratch ----------------
__device__ bf16 g_hw [(size_t)NTOK * CC];
__device__ bf16 g_qkv[(size_t)NTOK * 288];
__device__ bf16 g_att[(size_t)NTOK * CC];

// ---------------- helpers ----------------
__device__ __forceinline__ uint32_t smem_u32(const void* p) {
    uint32_t a;
    asm("{ .reg .u64 t; cvta.to.shared.u64 t, %1; cvt.u32.u64 %0, t; }" : "=r"(a) : "l"(p));
    return a;
}
__device__ __forceinline__ void cp16(void* d, const void* s) {
    asm volatile("cp.async.cg.shared.global [%0], [%1], 16;" :: "r"(smem_u32(d)), "l"(s));
}
#define CPC() asm volatile("cp.async.commit_group;" ::: "memory")
#define CPW() asm volatile("cp.async.wait_group 0;" ::: "memory")

__device__ __forceinline__ void ldm_x4(uint32_t& r0, uint32_t& r1, uint32_t& r2, uint32_t& r3, uint32_t addr) {
    asm volatile("ldmatrix.sync.aligned.m8n8.x4.shared.b16 {%0,%1,%2,%3}, [%4];"
                 : "=r"(r0), "=r"(r1), "=r"(r2), "=r"(r3) : "r"(addr));
}
__device__ __forceinline__ void ldm_x4t(uint32_t& r0, uint32_t& r1, uint32_t& r2, uint32_t& r3, uint32_t addr) {
    asm volatile("ldmatrix.sync.aligned.m8n8.x4.trans.shared.b16 {%0,%1,%2,%3}, [%4];"
                 : "=r"(r0), "=r"(r1), "=r"(r2), "=r"(r3) : "r"(addr));
}
__device__ __forceinline__ void mma16816(float* c, uint32_t a0, uint32_t a1, uint32_t a2, uint32_t a3,
                                         uint32_t b0, uint32_t b1) {
    asm volatile("mma.sync.aligned.m16n8k16.row.col.f32.bf16.bf16.f32 "
                 "{%0,%1,%2,%3}, {%4,%5,%6,%7}, {%8,%9}, {%0,%1,%2,%3};"
                 : "+f"(c[0]), "+f"(c[1]), "+f"(c[2]), "+f"(c[3])
                 : "r"(a0), "r"(a1), "r"(a2), "r"(a3), "r"(b0), "r"(b1));
}

__device__ __forceinline__ float wred(float v) {
    #pragma unroll
    for (int o = 16; o; o >>= 1) v += __shfl_xor_sync(0xffffffffu, v, o);
    return v;
}

__device__ __forceinline__ float fast_gelu(float x) {
    // tanh-form GELU via sigmoid: x * sigmoid(1.5957691*x + 0.07135481*x^3)
    float t = x * (1.5957691216057308f + 0.07135481627f * x * x);
    return x / (1.f + __expf(-t));
}

__device__ __forceinline__ int winrow_to_token(int row) {
    int n  = row % NN;  int w = row / NN;
    int wj = w % NWIN;  int t = w / NWIN;
    int wi = t % NWIN;  int bb = t / NWIN;
    int i = n / WSZ, j = n % WSZ;
    int r = wi*WSZ + i + SHIFTV; if (r >= HDIM) r -= HDIM;
    int c = wj*WSZ + j + SHIFTV; if (c >= HDIM) c -= HDIM;
    return bb*LL + r*HDIM + c;
}

// =====================================================================
// qkv kernel: fused LN1 + gather + GEMM (96->288)  [R5-bench version]
// =====================================================================
__global__ void __launch_bounds__(512, 1)
qkv_kernel(const float* __restrict__ x, const float* __restrict__ Wq,
           const float* __restrict__ bq, const float* __restrict__ g1,
           const float* __restrict__ b1, bf16* __restrict__ out)
{
    extern __shared__ __align__(16) char sm[];
    bf16*  sW   = (bf16*)sm;                       // 56832
    bf16*  sA   = (bf16*)(sm + 56832);             // 26624
    float* xst0 = (float*)(sm + 83456);            // 49152
    float* xst1 = (float*)(sm + 132608);           // 49152
    int*   stok = (int*)(sm + 181760);             // 1024
    float* sbias= (float*)(sm + 182784);           // 1152
    float* sg   = (float*)(sm + 183936);
    float* sb   = (float*)(sm + 184320);           // total 184704

    const int tid = threadIdx.x, warp = tid >> 5, lane = tid & 31;
    const int mw = warp >> 1, nw = warp & 1;

    for (int i = tid; i < 96*288; i += 512) { int k = i/288, n = i%288; sW[k*296+n] = __float2bfloat16(Wq[i]); }
    for (int i = tid; i < 288; i += 512) sbias[i] = bq[i];
    if (tid < 96) { sg[tid] = g1[tid]; sb[tid] = b1[tid]; }

    const uint32_t aBase = smem_u32(sA) + ((mw*16 + (lane & 15))*104 + (lane >> 4)*8) * 2;
    const uint32_t wBase = smem_u32(sW) + (((lane & 7) + ((lane >> 3) & 1)*8)*296 + (lane >> 4)*8) * 2;

    int tile = blockIdx.x, buf = 0;
    if (tid < 128) stok[tid] = winrow_to_token(tile*128 + tid);
    __syncthreads();
    for (int idx = tid; idx < 3072; idx += 512) {
        int r = idx/24, c = idx%24;
        cp16(xst0 + r*96 + c*4, x + (size_t)stok[r]*96 + c*4);
    }
    CPC();

    for (; tile < NUMTILES; tile += GRID) {
        CPW(); __syncthreads();
        float* xs = buf ? xst1 : xst0;

        #pragma unroll
        for (int rr = 0; rr < 8; rr++) {
            int r = warp*8 + rr;
            float v0 = xs[r*96+lane], v1 = xs[r*96+lane+32], v2 = xs[r*96+lane+64];
            float mu = wred(v0+v1+v2) * (1.f/96.f);
            float d0 = v0-mu, d1 = v1-mu, d2 = v2-mu;
            float var = wred(d0*d0 + d1*d1 + d2*d2) * (1.f/96.f);
            float rs = rsqrtf(var + 1e-5f);
            sA[r*104+lane]    = __float2bfloat16(d0*rs*sg[lane]    + sb[lane]);
            sA[r*104+lane+32] = __float2bfloat16(d1*rs*sg[lane+32] + sb[lane+32]);
            sA[r*104+lane+64] = __float2bfloat16(d2*rs*sg[lane+64] + sb[lane+64]);
        }
        int nt = tile + GRID;
        int nb = buf ^ 1;
        if (tid < 128 && nt < NUMTILES) stok[nb*128 + tid] = winrow_to_token(nt*128 + tid);
        __syncthreads();
        if (nt < NUMTILES) {
            float* xn = nb ? xst1 : xst0;
            const int* st = stok + nb*128;
            for (int idx = tid; idx < 3072; idx += 512) {
                int r = idx/24, c = idx%24;
                cp16(xn + r*96 + c*4, x + (size_t)st[r]*96 + c*4);
            }
        }
        CPC();

        const int r0 = tile*128 + mw*16 + (lane >> 2);
        const int cl = (lane & 3)*2;
        #pragma unroll
        for (int c = 0; c < 3; c++) {
            float acc[6][4];
            #pragma unroll
            for (int f = 0; f < 6; f++) { acc[f][0]=0.f; acc[f][1]=0.f; acc[f][2]=0.f; acc[f][3]=0.f; }
            #pragma unroll
            for (int ks = 0; ks < 6; ks++) {
                uint32_t a0,a1,a2,a3;
                ldm_x4(a0,a1,a2,a3, aBase + ks*32);
                #pragma unroll
                for (int p = 0; p < 3; p++) {
                    uint32_t b0,b1,b2,b3;
                    ldm_x4t(b0,b1,b2,b3, wBase + (ks*16*296 + c*96 + nw*48 + p*16)*2);
                    mma16816(acc[2*p],   a0,a1,a2,a3, b0,b1);
                    mma16816(acc[2*p+1], a0,a1,a2,a3, b2,b3);
                }
            }
            #pragma unroll
            for (int f = 0; f < 6; f++) {
                int col = c*96 + nw*48 + f*8 + cl;
                float bz0 = sbias[col], bz1 = sbias[col+1];
                __nv_bfloat162 p0 = __floats2bfloat162_rn(acc[f][0]+bz0, acc[f][1]+bz1);
                __nv_bfloat162 p1 = __floats2bfloat162_rn(acc[f][2]+bz0, acc[f][3]+bz1);
                *(uint32_t*)(out + (size_t)r0*288 + col)     = *(uint32_t*)&p0;
                *(uint32_t*)(out + (size_t)(r0+8)*288 + col) = *(uint32_t*)&p1;
            }
        }
        buf ^= 1;
    }
}

// =====================================================================
// proj kernel (WMMA + staging, LN2 fused) -- unchanged
// =====================================================================
__global__ void __launch_bounds__(512, 1)
proj_kernel(const bf16* __restrict__ A, const float* __restrict__ Wp,
            const float* __restrict__ bp, const float* __restrict__ x,
            const float* __restrict__ g2, const float* __restrict__ b2,
            float* __restrict__ y, bf16* __restrict__ hw)
{
    extern __shared__ __align__(16) char sm[];
    bf16*  sW   = (bf16*)sm;                        // 19968
    bf16*  sA0  = (bf16*)(sm + 19968);
    bf16*  sA1  = (bf16*)(sm + 46592);
    float* stag = (float*)(sm + 73216);             // 51200
    float* rst0 = (float*)(sm + 124416);
    float* rst1 = (float*)(sm + 173568);
    int*   stok = (int*)(sm + 222720);
    float* sbias= (float*)(sm + 223744);
    float* sg   = (float*)(sm + 224128);
    float* sb   = (float*)(sm + 224512);            // total 224896

    const int tid = threadIdx.x, warp = tid >> 5, lane = tid & 31;
    const int mw = warp >> 1, nw = warp & 1;

    for (int i = tid; i < 96*96; i += 512) { int k = i/96, n = i%96; sW[k*104+n] = __float2bfloat16(Wp[i]); }
    if (tid < 96) { sbias[tid] = bp[tid]; sg[tid] = g2[tid]; sb[tid] = b2[tid]; }

    int tile = blockIdx.x, buf = 0;
    if (tid < 128) stok[tid] = winrow_to_token(tile*128 + tid);
    __syncthreads();
    {
        const bf16* Ag = A + (size_t)tile*128*96;
        for (int idx = tid; idx < 1536; idx += 512) { int r = idx/12, c = idx%12; cp16(sA0 + r*104 + c*8, Ag + r*96 + c*8); }
        for (int idx = tid; idx < 3072; idx += 512) { int r = idx/24, c = idx%24; cp16(rst0 + r*96 + c*4, x + (size_t)stok[r]*96 + c*4); }
    }
    CPC();

    for (; tile < NUMTILES; tile += GRID) {
        CPW(); __syncthreads();
        bf16*  sA  = buf ? sA1 : sA0;
        float* rst = buf ? rst1 : rst0;

        int nt = tile + GRID;
        int nb = buf ^ 1;
        if (tid < 128 && nt < NUMTILES) stok[nb*128 + tid] = winrow_to_token(nt*128 + tid);
        __syncthreads();
        if (nt < NUMTILES) {
            bf16*  sAn  = nb ? sA1 : sA0;
            float* rstn = nb ? rst1 : rst0;
            const int* st = stok + nb*128;
            const bf16* Ag = A + (size_t)nt*128*96;
            for (int idx = tid; idx < 1536; idx += 512) { int r = idx/12, c = idx%12; cp16(sAn + r*104 + c*8, Ag + r*96 + c*8); }
            for (int idx = tid; idx < 3072; idx += 512) { int r = idx/24, c = idx%24; cp16(rstn + r*96 + c*4, x + (size_t)st[r]*96 + c*4); }
        }
        CPC();

        wmma::fragment<wmma::accumulator, 16, 16, 16, float> acc[3];
        #pragma unroll
        for (int f = 0; f < 3; f++) wmma::fill_fragment(acc[f], 0.f);
        #pragma unroll
        for (int ks = 0; ks < 6; ks++) {
            wmma::fragment<wmma::matrix_a, 16, 16, 16, bf16, wmma::row_major> af;
            wmma::load_matrix_sync(af, sA + (mw*16)*104 + ks*16, 104);
            #pragma unroll
            for (int f = 0; f < 3; f++) {
                wmma::fragment<wmma::matrix_b, 16, 16, 16, bf16, wmma::row_major> bfr;
                wmma::load_matrix_sync(bfr, sW + (ks*16)*104 + nw*48 + f*16, 104);
                wmma::mma_sync(acc[f], af, bfr, acc[f]);
            }
        }
        __syncthreads();
        #pragma unroll
        for (int f = 0; f < 3; f++)
            wmma::store_matrix_sync(stag + (mw*16)*100 + nw*48 + f*16, acc[f], 100, wmma::mem_row_major);
        __syncthreads();

        const int* st = stok + buf*128;
        #pragma unroll
        for (int rr = 0; rr < 8; rr++) {
            int r = warp*8 + rr;
            int tk = st[r];
            float a0 = stag[r*100+lane]    + sbias[lane]    + rst[r*96+lane];
            float a1 = stag[r*100+lane+32] + sbias[lane+32] + rst[r*96+lane+32];
            float a2 = stag[r*100+lane+64] + sbias[lane+64] + rst[r*96+lane+64];
            float mu = wred(a0+a1+a2) * (1.f/96.f);
            float d0 = a0-mu, d1 = a1-mu, d2 = a2-mu;
            float var = wred(d0*d0 + d1*d1 + d2*d2) * (1.f/96.f);
            float rs = rsqrtf(var + 1e-5f);
            size_t o = (size_t)tk * 96;
            y[o+lane]    = a0;  y[o+lane+32] = a1;  y[o+lane+64] = a2;
            hw[o+lane]    = __float2bfloat16(d0*rs*sg[lane]    + sb[lane]);
            hw[o+lane+32] = __float2bfloat16(d1*rs*sg[lane+32] + sb[lane+32]);
            hw[o+lane+64] = __float2bfloat16(d2*rs*sg[lane+64] + sb[lane+64]);
        }
        __syncthreads();
        buf ^= 1;
    }
}

// =====================================================================
// fused MLP kernel: fc1 + GELU + fc2 + residual, hidden never leaves regs
// 256 threads = 8 warps x 16 rows. Accumulator->A-operand relayout.
// =====================================================================
__global__ void __launch_bounds__(256, 1)
mlp_kernel(const bf16* __restrict__ A, const float* __restrict__ W1,
           const float* __restrict__ b1f, const float* __restrict__ W2,
           const float* __restrict__ b2f, float* __restrict__ y)
{
    extern __shared__ __align__(16) char sm[];
    bf16*  sW1  = (bf16*)sm;                        // 96*392*2  = 75264
    bf16*  sW2  = (bf16*)(sm + 75264);              // 384*104*2 = 79872
    bf16*  sA0  = (bf16*)(sm + 155136);             // 26624
    bf16*  sA1  = (bf16*)(sm + 181760);             // 26624
    float* sb1  = (float*)(sm + 208384);            // 1536
    float* sb2  = (float*)(sm + 209920);            // 384 (total 210304)

    const int tid = threadIdx.x, warp = tid >> 5, lane = tid & 31;

    for (int i = tid; i < 96*384; i += 256) { int k = i/384, n = i%384; sW1[k*392+n] = __float2bfloat16(W1[i]); }
    for (int i = tid; i < 384*96; i += 256) { int k = i/96,  n = i%96;  sW2[k*104+n] = __float2bfloat16(W2[i]); }
    for (int i = tid; i < 384; i += 256) sb1[i] = b1f[i];
    if (tid < 96) sb2[tid] = b2f[tid];

    const uint32_t aOff   = ((warp*16 + (lane & 15))*104 + (lane >> 4)*8) * 2;
    const uint32_t w1Base = smem_u32(sW1) + (((lane & 7) + ((lane >> 3) & 1)*8)*392 + (lane >> 4)*8) * 2;
    const uint32_t w2Base = smem_u32(sW2) + (((lane & 7) + ((lane >> 3) & 1)*8)*104 + (lane >> 4)*8) * 2;
    const int t2 = (lane & 3)*2;

    int tile = blockIdx.x, buf = 0;
    {
        const bf16* Ag = A + (size_t)tile*128*96;
        for (int idx = tid; idx < 1536; idx += 256) { int r = idx/12, c = idx%12; cp16(sA0 + r*104 + c*8, Ag + r*96 + c*8); }
    }
    CPC();
    __syncthreads();

    for (; tile < NUMTILES; tile += GRID) {
        CPW(); __syncthreads();
        uint32_t aBase = smem_u32(buf ? sA1 : sA0) + aOff;
        int nt = tile + GRID;
        if (nt < NUMTILES) {
            bf16* sAn = (buf^1) ? sA1 : sA0;
            const bf16* Ag = A + (size_t)nt*128*96;
            for (int idx = tid; idx < 1536; idx += 256) { int r = idx/12, c = idx%12; cp16(sAn + r*104 + c*8, Ag + r*96 + c*8); }
        }
        CPC();

        // load A fragments once (reused across all 24 hidden chunks)
        uint32_t areg[6][4];
        #pragma unroll
        for (int ks = 0; ks < 6; ks++)
            ldm_x4(areg[ks][0], areg[ks][1], areg[ks][2], areg[ks][3], aBase + ks*32);

        float acc2[12][4];
        #pragma unroll
        for (int p = 0; p < 12; p++) { acc2[p][0]=0.f; acc2[p][1]=0.f; acc2[p][2]=0.f; acc2[p][3]=0.f; }

        #pragma unroll 1
        for (int kc = 0; kc < 24; kc++) {
            // fc1: hidden chunk 16 rows x 16 cols (cols kc*16..+15)
            float h[8];
            #pragma unroll
            for (int i = 0; i < 8; i++) h[i] = 0.f;
            #pragma unroll
            for (int ks = 0; ks < 6; ks++) {
                uint32_t b0,b1,b2,b3;
                ldm_x4t(b0,b1,b2,b3, w1Base + (ks*16*392 + kc*16)*2);
                mma16816(h,   areg[ks][0], areg[ks][1], areg[ks][2], areg[ks][3], b0,b1);
                mma16816(h+4, areg[ks][0], areg[ks][1], areg[ks][2], areg[ks][3], b2,b3);
            }
            // bias + GELU + pack straight into fc2 A-fragments
            int c0 = kc*16 + t2;
            float z0 = sb1[c0], z1 = sb1[c0+1], z8 = sb1[c0+8], z9 = sb1[c0+9];
            float g0 = fast_gelu(h[0]+z0), g1 = fast_gelu(h[1]+z1);
            float g2 = fast_gelu(h[2]+z0), g3 = fast_gelu(h[3]+z1);
            float g4 = fast_gelu(h[4]+z8), g5 = fast_gelu(h[5]+z9);
            float g6 = fast_gelu(h[6]+z8), g7 = fast_gelu(h[7]+z9);
            __nv_bfloat162 q0 = __floats2bfloat162_rn(g0, g1);
            __nv_bfloat162 q1 = __floats2bfloat162_rn(g2, g3);
            __nv_bfloat162 q2 = __floats2bfloat162_rn(g4, g5);
            __nv_bfloat162 q3 = __floats2bfloat162_rn(g6, g7);
            uint32_t ha0 = *(uint32_t*)&q0, ha1 = *(uint32_t*)&q1;
            uint32_t ha2 = *(uint32_t*)&q2, ha3 = *(uint32_t*)&q3;
            // fc2: accumulate 12 n8 output blocks for this k-chunk
            #pragma unroll
            for (int p = 0; p < 6; p++) {
                uint32_t b0,b1,b2,b3;
                ldm_x4t(b0,b1,b2,b3, w2Base + (kc*16*104 + p*16)*2);
                mma16816(acc2[2*p],   ha0,ha1,ha2,ha3, b0,b1);
                mma16816(acc2[2*p+1], ha0,ha1,ha2,ha3, b2,b3);
            }
        }

        // epilogue: y += acc2 + bias2
        const int r0 = tile*128 + warp*16 + (lane >> 2);
        #pragma unroll
        for (int p = 0; p < 12; p++) {
            int col = p*8 + t2;
            float bz0 = sb2[col], bz1 = sb2[col+1];
            float2* p0 = (float2*)(y + (size_t)r0*96 + col);
            float2* p1 = (float2*)(y + (size_t)(r0+8)*96 + col);
            float2 v0 = *p0, v1 = *p1;
            v0.x += acc2[p][0] + bz0;  v0.y += acc2[p][1] + bz1;
            v1.x += acc2[p][2] + bz0;  v1.y += acc2[p][3] + bz1;
            *p0 = v0;  *p1 = v1;
        }
        buf ^= 1;
    }
}

// =====================================================================
// window attention (R5-bench version: 64 threads, q in registers)
// =====================================================================
__global__ void __launch_bounds__(64)
attn_kernel(const bf16* __restrict__ qkv, const float* __restrict__ rpb,
            float* __restrict__ attn_w, bf16* __restrict__ outp) {
    const int blk = blockIdx.x;
    const int h = blk % NHH, w = blk / NHH;
    __shared__ float sk[NN*HD], sv[NN*HD];
    __shared__ float srpb[169];
    __shared__ float s_a[NN*53];
    const int tid = threadIdx.x;

    const bf16* base = qkv + (size_t)w * NN * 288 + h*HD;
    for (int idx = tid; idx < NN*8; idx += 64) {
        int n = idx >> 3, p = idx & 7;
        int which = p >> 2, ch = p & 3;
        uint4 vv = *(const uint4*)(base + (size_t)n*288 + 96 + which*96 + ch*8);
        const __nv_bfloat162* b2 = (const __nv_bfloat162*)&vv;
        float* dst = (which == 0 ? sk : sv) + n*HD + ch*8;
        #pragma unroll
        for (int t = 0; t < 4; t++) { float2 f = __bfloat1622float2(b2[t]); dst[2*t] = f.x; dst[2*t+1] = f.y; }
    }
    for (int idx = tid; idx < 169; idx += 64) srpb[idx] = rpb[idx*NHH + h];
    __syncthreads();

    if (tid < NN) {
        const int n = tid, i1 = n / WSZ, j1 = n % WSZ;
        float q[HD];
        const bf16* qp = base + (size_t)n*288;
        #pragma unroll
        for (int t = 0; t < 4; t++) {
            uint4 vv = ((const uint4*)qp)[t];
            const __nv_bfloat162* b2 = (const __nv_bfloat162*)&vv;
            #pragma unroll
            for (int u = 0; u < 4; u++) {
                float2 f = __bfloat1622float2(b2[u]);
                q[t*8 + 2*u]     = f.x * SCALEV;
                q[t*8 + 2*u + 1] = f.y * SCALEV;
            }
        }
        const float4* sk4 = (const float4*)sk;
        float mx = -1e30f;
        for (int m = 0; m < NN; m++) {
            float s0 = 0.f, s1 = 0.f, s2 = 0.f, s3 = 0.f;
            #pragma unroll
            for (int i = 0; i < 8; i++) {
                float4 kk = sk4[m*8 + i];
                s0 += q[4*i]*kk.x; s1 += q[4*i+1]*kk.y; s2 += q[4*i+2]*kk.z; s3 += q[4*i+3]*kk.w;
            }
            int i2 = m / WSZ, j2 = m % WSZ;
            float dot = (s0 + s1) + (s2 + s3) + srpb[(i1 - i2 + 6)*13 + (j1 - j2 + 6)];
            s_a[n*53 + m] = dot;
            mx = fmaxf(mx, dot);
        }
        float ss = 0.f;
        for (int m = 0; m < NN; m++) { float e = __expf(s_a[n*53 + m] - mx); s_a[n*53 + m] = e; ss += e; }
        float inv = 1.f / ss;
        for (int m = 0; m < NN; m++) s_a[n*53 + m] *= inv;
    }
    __syncthreads();

    if (attn_w) {
        float* ap = attn_w + (size_t)(w*NHH + h) * (NN*NN);
        for (int idx = tid; idx < NN*NN; idx += 64) ap[idx] = s_a[(idx/NN)*53 + idx % NN];
    }

    if (tid < NN) {
        const int n = tid;
        float4 o[8];
        #pragma unroll
        for (int i = 0; i < 8; i++) { o[i].x = 0.f; o[i].y = 0.f; o[i].z = 0.f; o[i].w = 0.f; }
        const float4* sv4 = (const float4*)sv;
        for (int m = 0; m < NN; m++) {
            float a = s_a[n*53 + m];
            #pragma unroll
            for (int i = 0; i < 8; i++) {
                float4 vv = sv4[m*8 + i];
                o[i].x += a*vv.x; o[i].y += a*vv.y; o[i].z += a*vv.z; o[i].w += a*vv.w;
            }
        }
        bf16* op = outp + (size_t)(w*NN + n) * CC + h*HD;
        uint32_t pk[16];
        #pragma unroll
        for (int i = 0; i < 8; i++) {
            __nv_bfloat162 p0 = __floats2bfloat162_rn(o[i].x, o[i].y);
            __nv_bfloat162 p1 = __floats2bfloat162_rn(o[i].z, o[i].w);
            pk[2*i]   = *(uint32_t*)&p0;
            pk[2*i+1] = *(uint32_t*)&p1;
        }
        #pragma unroll
        for (int t = 0; t < 4; t++) ((uint4*)op)[t] = ((const uint4*)pk)[t];
    }
}

// ---------------- launch ----------------
extern "C" void kernel_launch(void* const* d_in, const int* in_sizes, int n_in,
                              void* d_out, int out_size) {
    const float* x      = (const float*)d_in[0];
    const float* w_qkv  = (const float*)d_in[1];
    const float* b_qkv  = (const float*)d_in[2];
    const float* w_proj = (const float*)d_in[3];
    const float* b_proj = (const float*)d_in[4];
    const float* rpb    = (const float*)d_in[5];
    const float* gamma1 = (const float*)d_in[6];
    const float* beta1  = (const float*)d_in[7];
    const float* gamma2 = (const float*)d_in[8];
    const float* beta2  = (const float*)d_in[9];
    const float* w_fc1  = (const float*)d_in[10];
    const float* b_fc1  = (const float*)d_in[11];
    const float* w_fc2  = (const float*)d_in[12];
    const float* b_fc2  = (const float*)d_in[13];

    float* y = (float*)d_out;
    float* attn_w = ((long long)out_size >= YE + AE) ? (y + YE) : (float*)0;

    bf16 *p_hw, *p_qkv, *p_att;
    cudaGetSymbolAddress((void**)&p_hw,  g_hw);
    cudaGetSymbolAddress((void**)&p_qkv, g_qkv);
    cudaGetSymbolAddress((void**)&p_att, g_att);

    const int SMQ = 184704, SMP = 224896, SMM = 210304;
    cudaFuncSetAttribute(qkv_kernel, cudaFuncAttributeMaxDynamicSharedMemorySize, SMQ);
    cudaFuncSetAttribute(proj_kernel, cudaFuncAttributeMaxDynamicSharedMemorySize, SMP);
    cudaFuncSetAttribute(mlp_kernel,  cudaFuncAttributeMaxDynamicSharedMemorySize, SMM);

    // 1) fused LN1 + gather + qkv GEMM
    qkv_kernel<<<GRID, 512, SMQ>>>(x, w_qkv, b_qkv, gamma1, beta1, p_qkv);
    // 2) window attention (+ attn weights)
    attn_kernel<<<BW*NHH, 64>>>(p_qkv, rpb, attn_w, p_att);
    // 3) proj GEMM + scatter + residual + LN2 -> y, hw
    proj_kernel<<<GRID, 512, SMP>>>(p_att, w_proj, b_proj, x, gamma2, beta2, y, p_hw);
    // 4) fused MLP: fc1 + GELU + fc2 + residual into y
    mlp_kernel<<<GRID, 256, SMM>>>(p_hw, w_fc1, b_fc1, w_fc2, b_fc2, y);
}

// round 8
// speedup vs baseline: 1.2035x; 1.1627x over previous
#include <cuda_runtime.h>
#include <cuda_bf16.h>
#include <mma.h>
#include <math.h>
#include <stdint.h>

using namespace nvcuda;
typedef __nv_bfloat16 bf16;

// ---------------- problem constants ----------------
#define Bc     16
#define HDIM   224
#define CC     96
#define LL     (HDIM*HDIM)
#define NTOK   (Bc*LL)              // 802816
#define WSZ    7
#define NN     49
#define NWIN   32
#define BW     (Bc*NWIN*NWIN)       // 16384
#define NHH    3
#define HD     32
#define MLPH   384
#define SHIFTV 3
#define SCALEV 0.17677669529663687f
#define NUMTILES (NTOK/128)         // 6272
#define NUMTILES2 (NTOK/256)        // 3136
#define GRID   148

static const long long YE = (long long)NTOK * CC;
static const long long AE = (long long)BW * NHH * NN * NN;

// ---------------- scratch ----------------
__device__ bf16 g_hw [(size_t)NTOK * CC];
__device__ bf16 g_qkv[(size_t)NTOK * 288];
__device__ bf16 g_att[(size_t)NTOK * CC];

// ---------------- helpers ----------------
__device__ __forceinline__ uint32_t smem_u32(const void* p) {
    uint32_t a;
    asm("{ .reg .u64 t; cvta.to.shared.u64 t, %1; cvt.u32.u64 %0, t; }" : "=r"(a) : "l"(p));
    return a;
}
__device__ __forceinline__ void cp16(void* d, const void* s) {
    asm volatile("cp.async.cg.shared.global [%0], [%1], 16;" :: "r"(smem_u32(d)), "l"(s));
}
#define CPC() asm volatile("cp.async.commit_group;" ::: "memory")
#define CPW() asm volatile("cp.async.wait_group 0;" ::: "memory")

__device__ __forceinline__ void ldm_x4(uint32_t& r0, uint32_t& r1, uint32_t& r2, uint32_t& r3, uint32_t addr) {
    asm volatile("ldmatrix.sync.aligned.m8n8.x4.shared.b16 {%0,%1,%2,%3}, [%4];"
                 : "=r"(r0), "=r"(r1), "=r"(r2), "=r"(r3) : "r"(addr));
}
__device__ __forceinline__ void ldm_x4t(uint32_t& r0, uint32_t& r1, uint32_t& r2, uint32_t& r3, uint32_t addr) {
    asm volatile("ldmatrix.sync.aligned.m8n8.x4.trans.shared.b16 {%0,%1,%2,%3}, [%4];"
                 : "=r"(r0), "=r"(r1), "=r"(r2), "=r"(r3) : "r"(addr));
}
__device__ __forceinline__ void mma16816(float* c, uint32_t a0, uint32_t a1, uint32_t a2, uint32_t a3,
                                         uint32_t b0, uint32_t b1) {
    asm volatile("mma.sync.aligned.m16n8k16.row.col.f32.bf16.bf16.f32 "
                 "{%0,%1,%2,%3}, {%4,%5,%6,%7}, {%8,%9}, {%0,%1,%2,%3};"
                 : "+f"(c[0]), "+f"(c[1]), "+f"(c[2]), "+f"(c[3])
                 : "r"(a0), "r"(a1), "r"(a2), "r"(a3), "r"(b0), "r"(b1));
}

__device__ __forceinline__ float wred(float v) {
    #pragma unroll
    for (int o = 16; o; o >>= 1) v += __shfl_xor_sync(0xffffffffu, v, o);
    return v;
}

__device__ __forceinline__ float fast_gelu(float x) {
    float t = x * (1.5957691216057308f + 0.07135481627f * x * x);
    return x / (1.f + __expf(-t));
}

__device__ __forceinline__ int winrow_to_token(int row) {
    int n  = row % NN;  int w = row / NN;
    int wj = w % NWIN;  int t = w / NWIN;
    int wi = t % NWIN;  int bb = t / NWIN;
    int i = n / WSZ, j = n % WSZ;
    int r = wi*WSZ + i + SHIFTV; if (r >= HDIM) r -= HDIM;
    int c = wj*WSZ + j + SHIFTV; if (c >= HDIM) c -= HDIM;
    return bb*LL + r*HDIM + c;
}

// =====================================================================
// qkv kernel: fused LN1 + gather + GEMM (96->288)
// =====================================================================
__global__ void __launch_bounds__(512, 1)
qkv_kernel(const float* __restrict__ x, const float* __restrict__ Wq,
           const float* __restrict__ bq, const float* __restrict__ g1,
           const float* __restrict__ b1, bf16* __restrict__ out)
{
    extern __shared__ __align__(16) char sm[];
    bf16*  sW   = (bf16*)sm;                       // 56832
    bf16*  sA   = (bf16*)(sm + 56832);             // 26624
    float* xst0 = (float*)(sm + 83456);            // 49152
    float* xst1 = (float*)(sm + 132608);           // 49152
    int*   stok = (int*)(sm + 181760);             // 1024
    float* sbias= (float*)(sm + 182784);           // 1152
    float* sg   = (float*)(sm + 183936);
    float* sb   = (float*)(sm + 184320);           // total 184704

    const int tid = threadIdx.x, warp = tid >> 5, lane = tid & 31;
    const int mw = warp >> 1, nw = warp & 1;

    for (int i = tid; i < 96*288; i += 512) { int k = i/288, n = i%288; sW[k*296+n] = __float2bfloat16(Wq[i]); }
    for (int i = tid; i < 288; i += 512) sbias[i] = bq[i];
    if (tid < 96) { sg[tid] = g1[tid]; sb[tid] = b1[tid]; }

    const uint32_t aBase = smem_u32(sA) + ((mw*16 + (lane & 15))*104 + (lane >> 4)*8) * 2;
    const uint32_t wBase = smem_u32(sW) + (((lane & 7) + ((lane >> 3) & 1)*8)*296 + (lane >> 4)*8) * 2;

    int tile = blockIdx.x, buf = 0;
    if (tid < 128) stok[tid] = winrow_to_token(tile*128 + tid);
    __syncthreads();
    for (int idx = tid; idx < 3072; idx += 512) {
        int r = idx/24, c = idx%24;
        cp16(xst0 + r*96 + c*4, x + (size_t)stok[r]*96 + c*4);
    }
    CPC();

    for (; tile < NUMTILES; tile += GRID) {
        CPW(); __syncthreads();
        float* xs = buf ? xst1 : xst0;

        #pragma unroll
        for (int rr = 0; rr < 8; rr++) {
            int r = warp*8 + rr;
            float v0 = xs[r*96+lane], v1 = xs[r*96+lane+32], v2 = xs[r*96+lane+64];
            float mu = wred(v0+v1+v2) * (1.f/96.f);
            float d0 = v0-mu, d1 = v1-mu, d2 = v2-mu;
            float var = wred(d0*d0 + d1*d1 + d2*d2) * (1.f/96.f);
            float rs = rsqrtf(var + 1e-5f);
            sA[r*104+lane]    = __float2bfloat16(d0*rs*sg[lane]    + sb[lane]);
            sA[r*104+lane+32] = __float2bfloat16(d1*rs*sg[lane+32] + sb[lane+32]);
            sA[r*104+lane+64] = __float2bfloat16(d2*rs*sg[lane+64] + sb[lane+64]);
        }
        int nt = tile + GRID;
        int nb = buf ^ 1;
        if (tid < 128 && nt < NUMTILES) stok[nb*128 + tid] = winrow_to_token(nt*128 + tid);
        __syncthreads();
        if (nt < NUMTILES) {
            float* xn = nb ? xst1 : xst0;
            const int* st = stok + nb*128;
            for (int idx = tid; idx < 3072; idx += 512) {
                int r = idx/24, c = idx%24;
                cp16(xn + r*96 + c*4, x + (size_t)st[r]*96 + c*4);
            }
        }
        CPC();

        const int r0 = tile*128 + mw*16 + (lane >> 2);
        const int cl = (lane & 3)*2;
        #pragma unroll
        for (int c = 0; c < 3; c++) {
            float acc[6][4];
            #pragma unroll
            for (int f = 0; f < 6; f++) { acc[f][0]=0.f; acc[f][1]=0.f; acc[f][2]=0.f; acc[f][3]=0.f; }
            #pragma unroll
            for (int ks = 0; ks < 6; ks++) {
                uint32_t a0,a1,a2,a3;
                ldm_x4(a0,a1,a2,a3, aBase + ks*32);
                #pragma unroll
                for (int p = 0; p < 3; p++) {
                    uint32_t b0,b1,b2,b3;
                    ldm_x4t(b0,b1,b2,b3, wBase + (ks*16*296 + c*96 + nw*48 + p*16)*2);
                    mma16816(acc[2*p],   a0,a1,a2,a3, b0,b1);
                    mma16816(acc[2*p+1], a0,a1,a2,a3, b2,b3);
                }
            }
            #pragma unroll
            for (int f = 0; f < 6; f++) {
                int col = c*96 + nw*48 + f*8 + cl;
                float bz0 = sbias[col], bz1 = sbias[col+1];
                __nv_bfloat162 p0 = __floats2bfloat162_rn(acc[f][0]+bz0, acc[f][1]+bz1);
                __nv_bfloat162 p1 = __floats2bfloat162_rn(acc[f][2]+bz0, acc[f][3]+bz1);
                *(uint32_t*)(out + (size_t)r0*288 + col)     = *(uint32_t*)&p0;
                *(uint32_t*)(out + (size_t)(r0+8)*288 + col) = *(uint32_t*)&p1;
            }
        }
        buf ^= 1;
    }
}

// =====================================================================
// proj kernel (WMMA + staging, LN2 fused) -- unchanged
// =====================================================================
__global__ void __launch_bounds__(512, 1)
proj_kernel(const bf16* __restrict__ A, const float* __restrict__ Wp,
            const float* __restrict__ bp, const float* __restrict__ x,
            const float* __restrict__ g2, const float* __restrict__ b2,
            float* __restrict__ y, bf16* __restrict__ hw)
{
    extern __shared__ __align__(16) char sm[];
    bf16*  sW   = (bf16*)sm;                        // 19968
    bf16*  sA0  = (bf16*)(sm + 19968);
    bf16*  sA1  = (bf16*)(sm + 46592);
    float* stag = (float*)(sm + 73216);             // 51200
    float* rst0 = (float*)(sm + 124416);
    float* rst1 = (float*)(sm + 173568);
    int*   stok = (int*)(sm + 222720);
    float* sbias= (float*)(sm + 223744);
    float* sg   = (float*)(sm + 224128);
    float* sb   = (float*)(sm + 224512);            // total 224896

    const int tid = threadIdx.x, warp = tid >> 5, lane = tid & 31;
    const int mw = warp >> 1, nw = warp & 1;

    for (int i = tid; i < 96*96; i += 512) { int k = i/96, n = i%96; sW[k*104+n] = __float2bfloat16(Wp[i]); }
    if (tid < 96) { sbias[tid] = bp[tid]; sg[tid] = g2[tid]; sb[tid] = b2[tid]; }

    int tile = blockIdx.x, buf = 0;
    if (tid < 128) stok[tid] = winrow_to_token(tile*128 + tid);
    __syncthreads();
    {
        const bf16* Ag = A + (size_t)tile*128*96;
        for (int idx = tid; idx < 1536; idx += 512) { int r = idx/12, c = idx%12; cp16(sA0 + r*104 + c*8, Ag + r*96 + c*8); }
        for (int idx = tid; idx < 3072; idx += 512) { int r = idx/24, c = idx%24; cp16(rst0 + r*96 + c*4, x + (size_t)stok[r]*96 + c*4); }
    }
    CPC();

    for (; tile < NUMTILES; tile += GRID) {
        CPW(); __syncthreads();
        bf16*  sA  = buf ? sA1 : sA0;
        float* rst = buf ? rst1 : rst0;

        int nt = tile + GRID;
        int nb = buf ^ 1;
        if (tid < 128 && nt < NUMTILES) stok[nb*128 + tid] = winrow_to_token(nt*128 + tid);
        __syncthreads();
        if (nt < NUMTILES) {
            bf16*  sAn  = nb ? sA1 : sA0;
            float* rstn = nb ? rst1 : rst0;
            const int* st = stok + nb*128;
            const bf16* Ag = A + (size_t)nt*128*96;
            for (int idx = tid; idx < 1536; idx += 512) { int r = idx/12, c = idx%12; cp16(sAn + r*104 + c*8, Ag + r*96 + c*8); }
            for (int idx = tid; idx < 3072; idx += 512) { int r = idx/24, c = idx%24; cp16(rstn + r*96 + c*4, x + (size_t)st[r]*96 + c*4); }
        }
        CPC();

        wmma::fragment<wmma::accumulator, 16, 16, 16, float> acc[3];
        #pragma unroll
        for (int f = 0; f < 3; f++) wmma::fill_fragment(acc[f], 0.f);
        #pragma unroll
        for (int ks = 0; ks < 6; ks++) {
            wmma::fragment<wmma::matrix_a, 16, 16, 16, bf16, wmma::row_major> af;
            wmma::load_matrix_sync(af, sA + (mw*16)*104 + ks*16, 104);
            #pragma unroll
            for (int f = 0; f < 3; f++) {
                wmma::fragment<wmma::matrix_b, 16, 16, 16, bf16, wmma::row_major> bfr;
                wmma::load_matrix_sync(bfr, sW + (ks*16)*104 + nw*48 + f*16, 104);
                wmma::mma_sync(acc[f], af, bfr, acc[f]);
            }
        }
        __syncthreads();
        #pragma unroll
        for (int f = 0; f < 3; f++)
            wmma::store_matrix_sync(stag + (mw*16)*100 + nw*48 + f*16, acc[f], 100, wmma::mem_row_major);
        __syncthreads();

        const int* st = stok + buf*128;
        #pragma unroll
        for (int rr = 0; rr < 8; rr++) {
            int r = warp*8 + rr;
            int tk = st[r];
            float a0 = stag[r*100+lane]    + sbias[lane]    + rst[r*96+lane];
            float a1 = stag[r*100+lane+32] + sbias[lane+32] + rst[r*96+lane+32];
            float a2 = stag[r*100+lane+64] + sbias[lane+64] + rst[r*96+lane+64];
            float mu = wred(a0+a1+a2) * (1.f/96.f);
            float d0 = a0-mu, d1 = a1-mu, d2 = a2-mu;
            float var = wred(d0*d0 + d1*d1 + d2*d2) * (1.f/96.f);
            float rs = rsqrtf(var + 1e-5f);
            size_t o = (size_t)tk * 96;
            y[o+lane]    = a0;  y[o+lane+32] = a1;  y[o+lane+64] = a2;
            hw[o+lane]    = __float2bfloat16(d0*rs*sg[lane]    + sb[lane]);
            hw[o+lane+32] = __float2bfloat16(d1*rs*sg[lane+32] + sb[lane+32]);
            hw[o+lane+64] = __float2bfloat16(d2*rs*sg[lane+64] + sb[lane+64]);
        }
        __syncthreads();
        buf ^= 1;
    }
}

// =====================================================================
// fused MLP kernel: fc1 + GELU + fc2 + residual, hidden in registers.
// 512 threads = 16 warps x 16 rows, M-tile 256, single A buffer with
// register-fragment prefetch overlap.
// =====================================================================
__global__ void __launch_bounds__(512, 1)
mlp_kernel(const bf16* __restrict__ A, const float* __restrict__ W1,
           const float* __restrict__ b1f, const float* __restrict__ W2,
           const float* __restrict__ b2f, float* __restrict__ y)
{
    extern __shared__ __align__(16) char sm[];
    bf16*  sW1  = (bf16*)sm;                        // 96*392*2  = 75264
    bf16*  sW2  = (bf16*)(sm + 75264);              // 384*104*2 = 79872
    bf16*  sA   = (bf16*)(sm + 155136);             // 256*104*2 = 53248
    float* sb1  = (float*)(sm + 208384);            // 1536
    float* sb2  = (float*)(sm + 209920);            // 384 (total 210304)

    const int tid = threadIdx.x, warp = tid >> 5, lane = tid & 31;

    for (int i = tid; i < 96*384; i += 512) { int k = i/384, n = i%384; sW1[k*392+n] = __float2bfloat16(W1[i]); }
    for (int i = tid; i < 384*96; i += 512) { int k = i/96,  n = i%96;  sW2[k*104+n] = __float2bfloat16(W2[i]); }
    for (int i = tid; i < 384; i += 512) sb1[i] = b1f[i];
    if (tid < 96) sb2[tid] = b2f[tid];

    const uint32_t aBase  = smem_u32(sA) + ((warp*16 + (lane & 15))*104 + (lane >> 4)*8) * 2;
    const uint32_t w1Base = smem_u32(sW1) + (((lane & 7) + ((lane >> 3) & 1)*8)*392 + (lane >> 4)*8) * 2;
    const uint32_t w2Base = smem_u32(sW2) + (((lane & 7) + ((lane >> 3) & 1)*8)*104 + (lane >> 4)*8) * 2;
    const int t2 = (lane & 3)*2;

    int tile = blockIdx.x;
    {   // prefetch tile 0 (256 rows x 96 cols = 3072 x 16B chunks)
        const bf16* Ag = A + (size_t)tile*256*96;
        for (int idx = tid; idx < 3072; idx += 512) { int r = idx/12, c = idx%12; cp16(sA + r*104 + c*8, Ag + r*96 + c*8); }
    }
    CPC();
    __syncthreads();

    for (; tile < NUMTILES2; tile += GRID) {
        CPW(); __syncthreads();

        // pull A fragments into registers (reused across all 24 k-chunks)
        uint32_t areg[6][4];
        #pragma unroll
        for (int ks = 0; ks < 6; ks++)
            ldm_x4(areg[ks][0], areg[ks][1], areg[ks][2], areg[ks][3], aBase + ks*32);
        __syncthreads();   // all warps done reading sA

        // prefetch NEXT tile into the same buffer while we compute
        int nt = tile + GRID;
        if (nt < NUMTILES2) {
            const bf16* Ag = A + (size_t)nt*256*96;
            for (int idx = tid; idx < 3072; idx += 512) { int r = idx/12, c = idx%12; cp16(sA + r*104 + c*8, Ag + r*96 + c*8); }
        }
        CPC();

        float acc2[12][4];
        #pragma unroll
        for (int p = 0; p < 12; p++) { acc2[p][0]=0.f; acc2[p][1]=0.f; acc2[p][2]=0.f; acc2[p][3]=0.f; }

        #pragma unroll 1
        for (int kc = 0; kc < 24; kc++) {
            float h[8];
            #pragma unroll
            for (int i = 0; i < 8; i++) h[i] = 0.f;
            #pragma unroll
            for (int ks = 0; ks < 6; ks++) {
                uint32_t b0,b1,b2,b3;
                ldm_x4t(b0,b1,b2,b3, w1Base + (ks*16*392 + kc*16)*2);
                mma16816(h,   areg[ks][0], areg[ks][1], areg[ks][2], areg[ks][3], b0,b1);
                mma16816(h+4, areg[ks][0], areg[ks][1], areg[ks][2], areg[ks][3], b2,b3);
            }
            int c0 = kc*16 + t2;
            float z0 = sb1[c0], z1 = sb1[c0+1], z8 = sb1[c0+8], z9 = sb1[c0+9];
            float g0 = fast_gelu(h[0]+z0), g1 = fast_gelu(h[1]+z1);
            float g2 = fast_gelu(h[2]+z0), g3 = fast_gelu(h[3]+z1);
            float g4 = fast_gelu(h[4]+z8), g5 = fast_gelu(h[5]+z9);
            float g6 = fast_gelu(h[6]+z8), g7 = fast_gelu(h[7]+z9);
            __nv_bfloat162 q0 = __floats2bfloat162_rn(g0, g1);
            __nv_bfloat162 q1 = __floats2bfloat162_rn(g2, g3);
            __nv_bfloat162 q2 = __floats2bfloat162_rn(g4, g5);
            __nv_bfloat162 q3 = __floats2bfloat162_rn(g6, g7);
            uint32_t ha0 = *(uint32_t*)&q0, ha1 = *(uint32_t*)&q1;
            uint32_t ha2 = *(uint32_t*)&q2, ha3 = *(uint32_t*)&q3;
            #pragma unroll
            for (int p = 0; p < 6; p++) {
                uint32_t b0,b1,b2,b3;
                ldm_x4t(b0,b1,b2,b3, w2Base + (kc*16*104 + p*16)*2);
                mma16816(acc2[2*p],   ha0,ha1,ha2,ha3, b0,b1);
                mma16816(acc2[2*p+1], ha0,ha1,ha2,ha3, b2,b3);
            }
        }

        const int r0 = tile*256 + warp*16 + (lane >> 2);
        #pragma unroll
        for (int p = 0; p < 12; p++) {
            int col = p*8 + t2;
            float bz0 = sb2[col], bz1 = sb2[col+1];
            float2* p0 = (float2*)(y + (size_t)r0*96 + col);
            float2* p1 = (float2*)(y + (size_t)(r0+8)*96 + col);
            float2 v0 = *p0, v1 = *p1;
            v0.x += acc2[p][0] + bz0;  v0.y += acc2[p][1] + bz1;
            v1.x += acc2[p][2] + bz0;  v1.y += acc2[p][3] + bz1;
            *p0 = v0;  *p1 = v1;
        }
    }
}

// =====================================================================
// window attention (64 threads, q in registers) -- unchanged
// =====================================================================
__global__ void __launch_bounds__(64)
attn_kernel(const bf16* __restrict__ qkv, const float* __restrict__ rpb,
            float* __restrict__ attn_w, bf16* __restrict__ outp) {
    const int blk = blockIdx.x;
    const int h = blk % NHH, w = blk / NHH;
    __shared__ float sk[NN*HD], sv[NN*HD];
    __shared__ float srpb[169];
    __shared__ float s_a[NN*53];
    const int tid = threadIdx.x;

    const bf16* base = qkv + (size_t)w * NN * 288 + h*HD;
    for (int idx = tid; idx < NN*8; idx += 64) {
        int n = idx >> 3, p = idx & 7;
        int which = p >> 2, ch = p & 3;
        uint4 vv = *(const uint4*)(base + (size_t)n*288 + 96 + which*96 + ch*8);
        const __nv_bfloat162* b2 = (const __nv_bfloat162*)&vv;
        float* dst = (which == 0 ? sk : sv) + n*HD + ch*8;
        #pragma unroll
        for (int t = 0; t < 4; t++) { float2 f = __bfloat1622float2(b2[t]); dst[2*t] = f.x; dst[2*t+1] = f.y; }
    }
    for (int idx = tid; idx < 169; idx += 64) srpb[idx] = rpb[idx*NHH + h];
    __syncthreads();

    if (tid < NN) {
        const int n = tid, i1 = n / WSZ, j1 = n % WSZ;
        float q[HD];
        const bf16* qp = base + (size_t)n*288;
        #pragma unroll
        for (int t = 0; t < 4; t++) {
            uint4 vv = ((const uint4*)qp)[t];
            const __nv_bfloat162* b2 = (const __nv_bfloat162*)&vv;
            #pragma unroll
            for (int u = 0; u < 4; u++) {
                float2 f = __bfloat1622float2(b2[u]);
                q[t*8 + 2*u]     = f.x * SCALEV;
                q[t*8 + 2*u + 1] = f.y * SCALEV;
            }
        }
        const float4* sk4 = (const float4*)sk;
        float mx = -1e30f;
        for (int m = 0; m < NN; m++) {
            float s0 = 0.f, s1 = 0.f, s2 = 0.f, s3 = 0.f;
            #pragma unroll
            for (int i = 0; i < 8; i++) {
                float4 kk = sk4[m*8 + i];
                s0 += q[4*i]*kk.x; s1 += q[4*i+1]*kk.y; s2 += q[4*i+2]*kk.z; s3 += q[4*i+3]*kk.w;
            }
            int i2 = m / WSZ, j2 = m % WSZ;
            float dot = (s0 + s1) + (s2 + s3) + srpb[(i1 - i2 + 6)*13 + (j1 - j2 + 6)];
            s_a[n*53 + m] = dot;
            mx = fmaxf(mx, dot);
        }
        float ss = 0.f;
        for (int m = 0; m < NN; m++) { float e = __expf(s_a[n*53 + m] - mx); s_a[n*53 + m] = e; ss += e; }
        float inv = 1.f / ss;
        for (int m = 0; m < NN; m++) s_a[n*53 + m] *= inv;
    }
    __syncthreads();

    if (attn_w) {
        float* ap = attn_w + (size_t)(w*NHH + h) * (NN*NN);
        for (int idx = tid; idx < NN*NN; idx += 64) ap[idx] = s_a[(idx/NN)*53 + idx % NN];
    }

    if (tid < NN) {
        const int n = tid;
        float4 o[8];
        #pragma unroll
        for (int i = 0; i < 8; i++) { o[i].x = 0.f; o[i].y = 0.f; o[i].z = 0.f; o[i].w = 0.f; }
        const float4* sv4 = (const float4*)sv;
        for (int m = 0; m < NN; m++) {
            float a = s_a[n*53 + m];
            #pragma unroll
            for (int i = 0; i < 8; i++) {
                float4 vv = sv4[m*8 + i];
                o[i].x += a*vv.x; o[i].y += a*vv.y; o[i].z += a*vv.z; o[i].w += a*vv.w;
            }
        }
        bf16* op = outp + (size_t)(w*NN + n) * CC + h*HD;
        uint32_t pk[16];
        #pragma unroll
        for (int i = 0; i < 8; i++) {
            __nv_bfloat162 p0 = __floats2bfloat162_rn(o[i].x, o[i].y);
            __nv_bfloat162 p1 = __floats2bfloat162_rn(o[i].z, o[i].w);
            pk[2*i]   = *(uint32_t*)&p0;
            pk[2*i+1] = *(uint32_t*)&p1;
        }
        #pragma unroll
        for (int t = 0; t < 4; t++) ((uint4*)op)[t] = ((const uint4*)pk)[t];
    }
}

// ---------------- launch ----------------
extern "C" void kernel_launch(void* const* d_in, const int* in_sizes, int n_in,
                              void* d_out, int out_size) {
    const float* x      = (const float*)d_in[0];
    const float* w_qkv  = (const float*)d_in[1];
    const float* b_qkv  = (const float*)d_in[2];
    const float* w_proj = (const float*)d_in[3];
    const float* b_proj = (const float*)d_in[4];
    const float* rpb    = (const float*)d_in[5];
    const float* gamma1 = (const float*)d_in[6];
    const float* beta1  = (const float*)d_in[7];
    const float* gamma2 = (const float*)d_in[8];
    const float* beta2  = (const float*)d_in[9];
    const float* w_fc1  = (const float*)d_in[10];
    const float* b_fc1  = (const float*)d_in[11];
    const float* w_fc2  = (const float*)d_in[12];
    const float* b_fc2  = (const float*)d_in[13];

    float* y = (float*)d_out;
    float* attn_w = ((long long)out_size >= YE + AE) ? (y + YE) : (float*)0;

    bf16 *p_hw, *p_qkv, *p_att;
    cudaGetSymbolAddress((void**)&p_hw,  g_hw);
    cudaGetSymbolAddress((void**)&p_qkv, g_qkv);
    cudaGetSymbolAddress((void**)&p_att, g_att);

    const int SMQ = 184704, SMP = 224896, SMM = 210304;
    cudaFuncSetAttribute(qkv_kernel, cudaFuncAttributeMaxDynamicSharedMemorySize, SMQ);
    cudaFuncSetAttribute(proj_kernel, cudaFuncAttributeMaxDynamicSharedMemorySize, SMP);
    cudaFuncSetAttribute(mlp_kernel,  cudaFuncAttributeMaxDynamicSharedMemorySize, SMM);

    // 1) fused LN1 + gather + qkv GEMM
    qkv_kernel<<<GRID, 512, SMQ>>>(x, w_qkv, b_qkv, gamma1, beta1, p_qkv);
    // 2) window attention (+ attn weights)
    attn_kernel<<<BW*NHH, 64>>>(p_qkv, rpb, attn_w, p_att);
    // 3) proj GEMM + scatter + residual + LN2 -> y, hw
    proj_kernel<<<GRID, 512, SMP>>>(p_att, w_proj, b_proj, x, gamma2, beta2, y, p_hw);
    // 4) fused MLP: fc1 + GELU + fc2 + residual into y (16 warps, M=256)
    mlp_kernel<<<GRID, 512, SMM>>>(p_hw, w_fc1, b_fc1, w_fc2, b_fc2, y);
}